// round 15
// baseline (speedup 1.0000x reference)
#include <cuda_runtime.h>
#include <cuda_bf16.h>
#include <math.h>
#include <stdint.h>

#define NB     2
#define NSEQ   256
#define NM     8
#define ND     256
#define NH     8
#define NDH    64
#define NINNER 512
#define NTOK   (NB*NSEQ*NM)          // 4096
#define NBN    (NB*NSEQ)             // 512
typedef __nv_bfloat16 bf16;
typedef __nv_bfloat162 bf162;

#define QSCALE 0.18033688011112042f   // 0.125 * log2(e): exp(S) == exp2(S')

// ---------------- scratch ----------------
__device__ float g_xt [NTOK*ND];
__device__ bf16  g_xtb[NTOK*ND];
__device__ bf16  g_qb [NTOK*NINNER];
__device__ bf16  g_kvb[NTOK*2*NINNER];
__device__ bf16  g_aob[(size_t)NBN*4096];
__device__ float g_wp [(size_t)4*NBN*2048];            // wout split-K partials (16.8MB)
__device__ float g_x2 [NTOK*ND];
__device__ bf16  g_x2b[NTOK*ND];
__device__ bf16  g_fib[(size_t)NTOK*1024];
__device__ float g_y2p[(size_t)2*NTOK*ND];             // ff2 split-K partials (8.4MB)
// bf16 weights
__device__ bf16  g_Wq  [256*512];
__device__ bf16  g_Wkv [256*1024];
__device__ bf16  g_Wout[(size_t)4096*2048];
__device__ bf16  g_Wff1[256*2048];
__device__ bf16  g_Wff2[1024*256];

// ---------------- ptx helpers ----------------
__device__ __forceinline__ uint32_t smaddr(const void* p) {
    return (uint32_t)__cvta_generic_to_shared(p);
}
__device__ __forceinline__ void cpa16(uint32_t dst, const void* src) {
    asm volatile("cp.async.cg.shared.global [%0], [%1], 16;\n" :: "r"(dst), "l"(src) : "memory");
}
__device__ __forceinline__ void cpa_commit() { asm volatile("cp.async.commit_group;\n" ::: "memory"); }
__device__ __forceinline__ void cpa_wait0()  { asm volatile("cp.async.wait_group 0;\n" ::: "memory"); }
__device__ __forceinline__ void cpa_wait1()  { asm volatile("cp.async.wait_group 1;\n" ::: "memory"); }

__device__ __forceinline__ void bar_sync(int id, int cnt) {
    asm volatile("bar.sync %0, %1;" :: "r"(id), "r"(cnt) : "memory");
}
__device__ __forceinline__ void bar_arrive(int id, int cnt) {
    asm volatile("bar.arrive %0, %1;" :: "r"(id), "r"(cnt) : "memory");
}
__device__ __forceinline__ float fex2(float x) {
    float r;
    asm("ex2.approx.f32 %0, %1;" : "=f"(r) : "f"(x));
    return r;
}

__device__ __forceinline__ void ldsm4(uint32_t& r0, uint32_t& r1, uint32_t& r2, uint32_t& r3, uint32_t a) {
    asm volatile("ldmatrix.sync.aligned.m8n8.x4.shared.b16 {%0,%1,%2,%3}, [%4];"
                 : "=r"(r0), "=r"(r1), "=r"(r2), "=r"(r3) : "r"(a));
}
__device__ __forceinline__ void ldsm2(uint32_t& r0, uint32_t& r1, uint32_t a) {
    asm volatile("ldmatrix.sync.aligned.m8n8.x2.shared.b16 {%0,%1}, [%2];"
                 : "=r"(r0), "=r"(r1) : "r"(a));
}
__device__ __forceinline__ void ldsm2t(uint32_t& r0, uint32_t& r1, uint32_t a) {
    asm volatile("ldmatrix.sync.aligned.m8n8.x2.trans.shared.b16 {%0,%1}, [%2];"
                 : "=r"(r0), "=r"(r1) : "r"(a));
}
__device__ __forceinline__ void mma_bf16(float* c, const uint32_t* a, const uint32_t* b) {
    asm volatile(
        "mma.sync.aligned.m16n8k16.row.col.f32.bf16.bf16.f32 "
        "{%0,%1,%2,%3}, {%4,%5,%6,%7}, {%8,%9}, {%0,%1,%2,%3};\n"
        : "+f"(c[0]), "+f"(c[1]), "+f"(c[2]), "+f"(c[3])
        : "r"(a[0]), "r"(a[1]), "r"(a[2]), "r"(a[3]), "r"(b[0]), "r"(b[1]));
}

// ---------------- dense GEMM building blocks (K-chunk 64, dynamic smem) ----------------
// A smem: [BM rows][144B] (64 bf16 + 16B pad). B smem: [64 rows][BN*2+16].

template<int BM, int BN>
__device__ __forceinline__ void g2s64(const bf16* __restrict__ A, int lda,
                                      const bf16* __restrict__ B, int ldb,
                                      int m0, int n0, int k0,
                                      uint32_t aB, uint32_t bB, int tid)
{
    #pragma unroll
    for (int i = tid; i < BM * 8; i += 256) {
        int r = i >> 3, c = i & 7;
        cpa16(aB + r * 144 + c * 16, A + (size_t)(m0 + r) * lda + k0 + c * 8);
    }
    constexpr int NC = BN / 8, SBv = BN * 2 + 16;
    #pragma unroll
    for (int i = tid; i < 64 * NC; i += 256) {
        int kr = i / NC, c = i % NC;
        cpa16(bB + kr * SBv + c * 16, B + (size_t)(k0 + kr) * ldb + n0 + c * 8);
    }
    cpa_commit();
}

template<int BM, int BN>
__device__ __forceinline__ void smma64(uint32_t aB, uint32_t bB, int lane,
                                       int wm0, int wn0, float acc[][BN/32][4])
{
    constexpr int MT = BM / 32, NT = BN / 32, SBv = BN * 2 + 16;
    #pragma unroll
    for (int s = 0; s < 4; s++) {
        uint32_t af[MT][4], bf2[NT][2];
        #pragma unroll
        for (int mi = 0; mi < MT; mi++)
            ldsm4(af[mi][0], af[mi][1], af[mi][2], af[mi][3],
                  aB + (wm0 + mi * 16 + (lane & 15)) * 144 + s * 32 + (lane & 16));
        #pragma unroll
        for (int ni = 0; ni < NT; ni++)
            ldsm2t(bf2[ni][0], bf2[ni][1],
                   bB + (s * 16 + (lane & 15)) * SBv + (wn0 + ni * 8) * 2);
        #pragma unroll
        for (int mi = 0; mi < MT; mi++)
            #pragma unroll
            for (int ni = 0; ni < NT; ni++)
                mma_bf16(acc[mi][ni], af[mi], bf2[ni]);
    }
}

template<int BM, int BN>
__device__ __forceinline__ void mma_loop(const bf16* __restrict__ A, int lda,
                                         const bf16* __restrict__ B, int ldb,
                                         int K, int m0, int n0,
                                         float acc[][BN/32][4],
                                         unsigned char* sAbuf, unsigned char* sBbuf)
{
    constexpr int SBv = BN * 2 + 16;
    const int tid = threadIdx.x, lane = tid & 31, warp = tid >> 5;
    const int wm0 = (warp >> 2) * (BM / 2), wn0 = (warp & 3) * (BN / 4);
    uint32_t aB0 = smaddr(sAbuf), aB1 = aB0 + BM * 144;
    uint32_t bB0 = smaddr(sBbuf), bB1 = bB0 + 64 * SBv;

    g2s64<BM, BN>(A, lda, B, ldb, m0, n0, 0, aB0, bB0, tid);
    const int nch = K >> 6;
    for (int i = 0; i < nch; i++) {
        cpa_wait0();
        __syncthreads();
        uint32_t aB = (i & 1) ? aB1 : aB0, bB = (i & 1) ? bB1 : bB0;
        if (i + 1 < nch)
            g2s64<BM, BN>(A, lda, B, ldb, m0, n0, (i + 1) * 64,
                          (i & 1) ? aB0 : aB1, (i & 1) ? bB0 : bB1, tid);
        smma64<BM, BN>(aB, bB, lane, wm0, wn0, acc);
        __syncthreads();
    }
}

// smem budgets
#define SM_QKV  (2*128*144 + 2*64*272)   // 71680
#define SM_G64  (2*128*144 + 2*64*144)   // 55296

// ---------------- epilogue helpers ----------------
template<int BM, int BN>
__device__ __forceinline__ void epi_f32(float acc[][BN/32][4], float* C, int ldc,
                                        int m0, int n0, const float* bias)
{
    const int lane = threadIdx.x & 31, warp = threadIdx.x >> 5;
    const int lr = lane >> 2, lc = lane & 3;
    const int wm0 = (warp >> 2) * (BM / 2), wn0 = (warp & 3) * (BN / 4);
    #pragma unroll
    for (int mi = 0; mi < BM / 32; mi++) {
        int row = m0 + wm0 + mi * 16 + lr;
        #pragma unroll
        for (int ni = 0; ni < BN / 32; ni++) {
            int col = n0 + wn0 + ni * 8 + 2 * lc;
            float bx = 0.f, by = 0.f;
            if (bias) { bx = bias[col]; by = bias[col + 1]; }
            *(float2*)(C + (size_t)row * ldc + col) =
                make_float2(acc[mi][ni][0] + bx, acc[mi][ni][1] + by);
            *(float2*)(C + (size_t)(row + 8) * ldc + col) =
                make_float2(acc[mi][ni][2] + bx, acc[mi][ni][3] + by);
        }
    }
}

template<int BM, int BN>
__device__ __forceinline__ void epi_bf16(float acc[][BN/32][4], bf16* C, int ldc,
                                         int m0, int n0, float alpha)
{
    const int lane = threadIdx.x & 31, warp = threadIdx.x >> 5;
    const int lr = lane >> 2, lc = lane & 3;
    const int wm0 = (warp >> 2) * (BM / 2), wn0 = (warp & 3) * (BN / 4);
    #pragma unroll
    for (int mi = 0; mi < BM / 32; mi++) {
        int row = m0 + wm0 + mi * 16 + lr;
        #pragma unroll
        for (int ni = 0; ni < BN / 32; ni++) {
            int col = n0 + wn0 + ni * 8 + 2 * lc;
            *(bf162*)(C + (size_t)row * ldc + col) =
                __floats2bfloat162_rn(acc[mi][ni][0] * alpha, acc[mi][ni][1] * alpha);
            *(bf162*)(C + (size_t)(row + 8) * ldc + col) =
                __floats2bfloat162_rn(acc[mi][ni][2] * alpha, acc[mi][ni][3] * alpha);
        }
    }
}

// ---------------- kernels ----------------

// merged: small weight conversions (Wq/Wkv/Wff1/Wff2) + input transpose.
__global__ __launch_bounds__(256) void k_prep(const float4* __restrict__ Wq,
                                              const float4* __restrict__ Wkv,
                                              const float4* __restrict__ Wff1,
                                              const float4* __restrict__ Wff2,
                                              const float* __restrict__ x)
{
    if (blockIdx.x < 1152) {
        int i = blockIdx.x * 256 + threadIdx.x;
        const float4* src; bf162* dst; int off;
        if      (i < 32768)  { src = Wq;   dst = (bf162*)g_Wq;   off = 0; }
        else if (i < 98304)  { src = Wkv;  dst = (bf162*)g_Wkv;  off = 32768; }
        else if (i < 229376) { src = Wff1; dst = (bf162*)g_Wff1; off = 98304; }
        else                 { src = Wff2; dst = (bf162*)g_Wff2; off = 229376; }
        int j = i - off;
        float4 v = src[j];
        dst[2 * j]     = __floats2bfloat162_rn(v.x, v.y);
        dst[2 * j + 1] = __floats2bfloat162_rn(v.z, v.w);
        return;
    }
    __shared__ float tile[32][33];
    int bi = blockIdx.x - 1152;
    int bx = bi & 7, by = (bi >> 3) & 7, zi = bi >> 6;
    int b = zi >> 3, m = zi & 7;
    int n0 = bx * 32, d0 = by * 32;
    int tx = threadIdx.x & 31, ty = threadIdx.x >> 5;
    #pragma unroll
    for (int r = 0; r < 4; r++) {
        int d = d0 + ty + r * 8;
        tile[ty + r * 8][tx] =
            x[((size_t)(b * ND + d) * NM + m) * NSEQ + n0 + tx];
    }
    __syncthreads();
    #pragma unroll
    for (int r = 0; r < 4; r++) {
        int n = n0 + ty + r * 8;
        int d = d0 + tx;
        float v = tile[tx][ty + r * 8];
        size_t o = ((size_t)(b * NSEQ + n) * NM + m) * ND + d;
        g_xt[o]  = v;
        g_xtb[o] = __float2bfloat16(v);
    }
}

// fused Q + KV projection. blockIdx.x<4 -> Q tile (x QSCALE), else KV tile.
__global__ __launch_bounds__(256) void k_qkv() {
    extern __shared__ unsigned char dsm[];
    unsigned char* sA = dsm;
    unsigned char* sB = dsm + 2 * 128 * 144;
    float acc[4][4][4] = {};
    int m0 = blockIdx.y * 128;
    if (blockIdx.x < 4) {
        int n0 = blockIdx.x * 128;
        mma_loop<128, 128>(g_xtb, ND, g_Wq, NINNER, ND, m0, n0, acc, sA, sB);
        epi_bf16<128, 128>(acc, g_qb, NINNER, m0, n0, QSCALE);
    } else {
        int n0 = (blockIdx.x - 4) * 128;
        mma_loop<128, 128>(g_xtb, ND, g_Wkv, 2 * NINNER, ND, m0, n0, acc, sA, sB);
        epi_bf16<128, 128>(acc, g_kvb, 2 * NINNER, m0, n0, 1.f);
    }
}

// ============ warp-specialized fused attention + hidden Wout conversion ============
// Blocks 0-127: attention. Blocks 128-147: convert Wout fp32->bf16 on idle SMs.
#define SATT_K    0
#define SATT_Q0   36864
#define SATT_Q1   73728
#define SATT_P0   110592
#define SATT_P1   147456
#define SATT_V0   184320
#define SATT_V1   193536
#define SATT_PART 202752
#define SATT_RSC  204800
#define SATT_SZ   205056
// barrier ids: FULL0=1 FULL1=2 EMPTY0=3 EMPTY1=4, producer-local=5, consumer-local=6

__global__ void __launch_bounds__(512, 1) k_attn(const float4* __restrict__ WoutSrc) {
    if (blockIdx.x >= 128) {
        const size_t total = (size_t)4096 * 2048 / 4;
        bf162* dst = (bf162*)g_Wout;
        for (size_t i = (size_t)(blockIdx.x - 128) * 512 + threadIdx.x;
             i < total; i += (size_t)20 * 512) {
            float4 v = WoutSrc[i];
            dst[2 * i]     = __floats2bfloat162_rn(v.x, v.y);
            dst[2 * i + 1] = __floats2bfloat162_rn(v.z, v.w);
        }
        return;
    }
    extern __shared__ unsigned char smem[];
    const uint32_t base = smaddr(smem);
    const int tid = threadIdx.x, lane = tid & 31, warp = tid >> 5;
    const int lr = lane >> 2, lc = lane & 3;
    const int e = blockIdx.x;
    const int z = e & 7, h = (e >> 3) & 7, b = e >> 6;

    const bf16* Qe = g_qb  + (size_t)(b * 2048) * 512  + h * 64;
    const bf16* Ke = g_kvb + (size_t)(b * 2048) * 1024 + h * 64;
    const bf16* Ve = g_kvb + (size_t)(b * 2048) * 1024 + 512 + h * 64;
    float* part = (float*)(smem + SATT_PART);
    float* rsc  = (float*)(smem + SATT_RSC);

    const uint32_t qB[2] = { base + SATT_Q0, base + SATT_Q1 };
    const uint32_t pB[2] = { base + SATT_P0, base + SATT_P1 };
    const uint32_t vB[2] = { base + SATT_V0, base + SATT_V1 };

    if (warp < 8) {
        // ---------------- PRODUCER ----------------
        const int ptid = tid;
        const int wm = warp >> 1, wn = warp & 1;
        auto loadK = [&]() {
            #pragma unroll
            for (int q = 0; q < 8; q++) {
                int idx = ptid + q * 256, row = idx >> 3, cc = idx & 7;
                cpa16(base + SATT_K + row * 144 + cc * 16,
                      Ke + (size_t)(row * 8 + z) * 1024 + cc * 8);
            }
        };
        auto loadQ = [&](int m, uint32_t dst) {
            #pragma unroll
            for (int q = 0; q < 8; q++) {
                int idx = ptid + q * 256, row = idx >> 3, cc = idx & 7;
                cpa16(dst + row * 144 + cc * 16,
                      Qe + (size_t)(row * 8 + m) * 512 + cc * 8);
            }
        };
        loadK();
        loadQ(0, qB[0]);
        cpa_commit();

        for (int c = 0; c < 32; c++) {
            const int m = c >> 2, j0 = (c & 3) << 6, s = c & 1;
            if ((c & 3) == 0) {
                if (m < 7) loadQ(m + 1, qB[(m + 1) & 1]);
                cpa_commit();
                cpa_wait1();
                bar_sync(5, 256);
            }
            bar_sync(3 + s, 512);
            const uint32_t qb = qB[m & 1];
            float sa[4][4][4] = {};
            #pragma unroll
            for (int s4 = 0; s4 < 4; s4++) {
                uint32_t af[4][4], bf2[4][2];
                #pragma unroll
                for (int mi = 0; mi < 4; mi++)
                    ldsm4(af[mi][0], af[mi][1], af[mi][2], af[mi][3],
                          qb + (wm * 64 + mi * 16 + (lane & 15)) * 144 + s4 * 32 + (lane & 16));
                #pragma unroll
                for (int ni = 0; ni < 4; ni++)
                    ldsm2(bf2[ni][0], bf2[ni][1],
                          base + SATT_K + (j0 + wn * 32 + ni * 8 + (lane & 7)) * 144
                          + s4 * 32 + ((lane >> 3) & 1) * 16);
                #pragma unroll
                for (int mi = 0; mi < 4; mi++)
                    #pragma unroll
                    for (int ni = 0; ni < 4; ni++)
                        mma_bf16(sa[mi][ni], af[mi], bf2[ni]);
            }
            float cs[4][2];
            #pragma unroll
            for (int ni = 0; ni < 4; ni++) { cs[ni][0] = 0.f; cs[ni][1] = 0.f; }
            #pragma unroll
            for (int mi = 0; mi < 4; mi++)
                #pragma unroll
                for (int ni = 0; ni < 4; ni++) {
                    float p0 = fex2(sa[mi][ni][0]);
                    float p1 = fex2(sa[mi][ni][1]);
                    float p2 = fex2(sa[mi][ni][2]);
                    float p3 = fex2(sa[mi][ni][3]);
                    sa[mi][ni][0] = p0; sa[mi][ni][1] = p1;
                    sa[mi][ni][2] = p2; sa[mi][ni][3] = p3;
                    cs[ni][0] += p0 + p2; cs[ni][1] += p1 + p3;
                }
            #pragma unroll
            for (int ni = 0; ni < 4; ni++) {
                float a = cs[ni][0], bq = cs[ni][1];
                #pragma unroll
                for (int o = 4; o <= 16; o <<= 1) {
                    a  += __shfl_xor_sync(0xffffffffu, a,  o);
                    bq += __shfl_xor_sync(0xffffffffu, bq, o);
                }
                if (lane < 4) {
                    int col = wn * 32 + ni * 8 + 2 * lane;
                    part[s * 256 + col * 4 + wm]       = a;
                    part[s * 256 + (col + 1) * 4 + wm] = bq;
                }
            }
            const uint32_t po = (s ? SATT_P1 : SATT_P0);
            #pragma unroll
            for (int ni = 0; ni < 4; ni++) {
                int col = wn * 32 + ni * 8 + 2 * lc;
                #pragma unroll
                for (int mi = 0; mi < 4; mi++) {
                    int row = wm * 64 + mi * 16 + lr;
                    *(bf162*)(smem + po + row * 144 + col * 2) =
                        __floats2bfloat162_rn(sa[mi][ni][0], sa[mi][ni][1]);
                    *(bf162*)(smem + po + (row + 8) * 144 + col * 2) =
                        __floats2bfloat162_rn(sa[mi][ni][2], sa[mi][ni][3]);
                }
            }
            bar_arrive(1 + s, 512);
        }
    } else {
        // ---------------- CONSUMER ----------------
        const int ctid = tid - 256;
        const int cw = warp - 8;
        const int wm = cw >> 1, wn = cw & 1;
        auto loadV = [&](int m, int j0, uint32_t dst) {
            #pragma unroll
            for (int q = 0; q < 2; q++) {
                int idx = ctid + q * 256, row = idx >> 3, cc = idx & 7;
                cpa16(dst + row * 144 + cc * 16,
                      Ve + (size_t)((j0 + row) * 8 + m) * 1024 + cc * 8);
            }
        };
        bar_arrive(3, 512);
        bar_arrive(4, 512);
        loadV(0, 0, vB[0]);
        cpa_commit();

        float oacc[4][4][4] = {};
        for (int c = 0; c < 32; c++) {
            const int s = c & 1;
            bar_sync(1 + s, 512);
            if (c < 31) {
                int cn = c + 1;
                loadV(cn >> 2, (cn & 3) << 6, vB[cn & 1]);
                cpa_commit();
                cpa_wait1();
            } else {
                cpa_wait0();
            }
            if (ctid < 64)
                rsc[ctid] = 1.f / (part[s * 256 + 4 * ctid]     + part[s * 256 + 4 * ctid + 1]
                                 + part[s * 256 + 4 * ctid + 2] + part[s * 256 + 4 * ctid + 3]);
            bar_sync(6, 256);
            const uint32_t vb = vB[s], pb = pB[s];
            {
                #pragma unroll
                for (int q = 0; q < 2; q++) {
                    int idx = ctid + q * 256, row = idx >> 3, cc = idx & 7;
                    float r = rsc[row];
                    bf162* vp2 = (bf162*)(smem + (vb - base) + row * 144 + cc * 16);
                    #pragma unroll
                    for (int qq = 0; qq < 4; qq++) {
                        float2 f = __bfloat1622float2(vp2[qq]);
                        f.x *= r; f.y *= r;
                        vp2[qq] = __float22bfloat162_rn(f);
                    }
                }
            }
            bar_sync(6, 256);
            #pragma unroll
            for (int s4 = 0; s4 < 4; s4++) {
                uint32_t af[4][4], bf2[4][2];
                #pragma unroll
                for (int mi = 0; mi < 4; mi++)
                    ldsm4(af[mi][0], af[mi][1], af[mi][2], af[mi][3],
                          pb + (wm * 64 + mi * 16 + (lane & 15)) * 144 + s4 * 32 + (lane & 16));
                #pragma unroll
                for (int ni = 0; ni < 4; ni++)
                    ldsm2t(bf2[ni][0], bf2[ni][1],
                           vb + (s4 * 16 + (lane & 15)) * 144 + (wn * 32 + ni * 8) * 2);
                #pragma unroll
                for (int mi = 0; mi < 4; mi++)
                    #pragma unroll
                    for (int ni = 0; ni < 4; ni++)
                        mma_bf16(oacc[mi][ni], af[mi], bf2[ni]);
            }
            bar_arrive(3 + s, 512);
        }
        bf16* Ob = g_aob + (size_t)(b * 256) * 4096 + z * 512 + h * 64;
        #pragma unroll
        for (int mi = 0; mi < 4; mi++) {
            int row = wm * 64 + mi * 16 + lr;
            #pragma unroll
            for (int ni = 0; ni < 4; ni++) {
                int col = wn * 32 + ni * 8 + 2 * lc;
                *(bf162*)(Ob + (size_t)row * 4096 + col) =
                    __floats2bfloat162_rn(oacc[mi][ni][0], oacc[mi][ni][1]);
                *(bf162*)(Ob + (size_t)(row + 8) * 4096 + col) =
                    __floats2bfloat162_rn(oacc[mi][ni][2], oacc[mi][ni][3]);
            }
        }
    }
}

// Wout split-K x4, 128x128 tiles: partial GEMM over K slice -> g_wp[z]
__global__ __launch_bounds__(256) void k_wout() {
    extern __shared__ unsigned char dsm[];
    unsigned char* sA = dsm;
    unsigned char* sB = dsm + 2 * 128 * 144;
    float acc[4][4][4] = {};
    int m0 = blockIdx.y * 128, n0 = blockIdx.x * 128;
    int ks = blockIdx.z * 1024;
    mma_loop<128, 128>(g_aob + ks, 4096, g_Wout + (size_t)ks * 2048, 2048,
                       1024, m0, n0, acc, sA, sB);
    epi_f32<128, 128>(acc, g_wp + (size_t)blockIdx.z * NBN * 2048, 2048, m0, n0, nullptr);
}

// residual + LayerNorm with split-K partial reduction.
__global__ __launch_bounds__(256) void k_ln(int mode,
                                            const float* __restrict__ g,
                                            const float* __restrict__ beta,
                                            const float* __restrict__ bias,
                                            float* __restrict__ out) {
    int t = blockIdx.x, d = threadIdx.x;
    float xv, yv;
    if (mode == 1) {
        int bn = t >> 3, m = t & 7;
        size_t idx = (size_t)bn * 2048 + m * 256 + d;
        xv = g_xt[(size_t)t * ND + d];
        yv = g_wp[idx] + g_wp[idx + (size_t)NBN * 2048]
           + g_wp[idx + (size_t)2 * NBN * 2048] + g_wp[idx + (size_t)3 * NBN * 2048]
           + bias[m * 256 + d];
    } else {
        size_t idx = (size_t)t * ND + d;
        xv = g_x2[idx];
        yv = g_y2p[idx] + g_y2p[idx + (size_t)NTOK * ND] + bias[d];
    }
    float v = xv + yv;
    float s = v, s2 = v * v;
    #pragma unroll
    for (int o = 16; o; o >>= 1) {
        s  += __shfl_xor_sync(0xffffffffu, s,  o);
        s2 += __shfl_xor_sync(0xffffffffu, s2, o);
    }
    __shared__ float sh[16];
    int w = d >> 5, l = d & 31;
    if (l == 0) { sh[w] = s; sh[8 + w] = s2; }
    __syncthreads();
    if (d == 0) {
        float ts = 0.f, ts2 = 0.f;
        #pragma unroll
        for (int i = 0; i < 8; i++) { ts += sh[i]; ts2 += sh[8 + i]; }
        float mu  = ts * (1.f / 256.f);
        float var = ts2 * (1.f / 256.f) - mu * mu;
        sh[0] = mu;
        sh[1] = rsqrtf(var + 1e-5f);
    }
    __syncthreads();
    float r = (v - sh[0]) * sh[1] * g[d] + beta[d];
    if (mode == 1) {
        g_x2 [(size_t)t * ND + d] = r;
        g_x2b[(size_t)t * ND + d] = __float2bfloat16(r);
    } else {
        out[(size_t)t * ND + d] = r;
    }
}

__global__ __launch_bounds__(256) void k_ff1g(const float* __restrict__ bias) {
    extern __shared__ unsigned char dsm[];
    unsigned char* sA = dsm;
    unsigned char* sB = dsm + 2 * 128 * 144;
    float aA[4][2][4] = {};
    float aG[4][2][4] = {};
    int m0 = blockIdx.y * 128, n0 = blockIdx.x * 64;
    mma_loop<128, 64>(g_x2b, ND, g_Wff1, 2048, ND, m0, n0,        aA, sA, sB);
    mma_loop<128, 64>(g_x2b, ND, g_Wff1, 2048, ND, m0, n0 + 1024, aG, sA, sB);

    const int lane = threadIdx.x & 31, warp = threadIdx.x >> 5;
    const int lr = lane >> 2, lc = lane & 3;
    const int wm0 = (warp >> 2) * 64, wn0 = (warp & 3) * 16;
    #pragma unroll
    for (int mi = 0; mi < 4; mi++) {
        int row = m0 + wm0 + mi * 16 + lr;
        #pragma unroll
        for (int ni = 0; ni < 2; ni++) {
            int col = n0 + wn0 + ni * 8 + 2 * lc;
            float ba0 = bias[col],        ba1 = bias[col + 1];
            float bg0 = bias[1024 + col], bg1 = bias[1024 + col + 1];
            #pragma unroll
            for (int half = 0; half < 2; half++) {
                int r = row + half * 8;
                float a0 = aA[mi][ni][2 * half + 0] + ba0;
                float a1 = aA[mi][ni][2 * half + 1] + ba1;
                float gt0 = aG[mi][ni][2 * half + 0] + bg0;
                float gt1 = aG[mi][ni][2 * half + 1] + bg1;
                float v0 = a0 * 0.5f * gt0 * (1.f + erff(gt0 * 0.70710678118654752f));
                float v1 = a1 * 0.5f * gt1 * (1.f + erff(gt1 * 0.70710678118654752f));
                *(bf162*)(g_fib + (size_t)r * 1024 + col) = __floats2bfloat162_rn(v0, v1);
            }
        }
    }
}

// FF2 split-K x2: partial GEMM over K slice -> g_y2p[z]
__global__ __launch_bounds__(256) void k_ff2() {
    extern __shared__ unsigned char dsm[];
    unsigned char* sA = dsm;
    unsigned char* sB = dsm + 2 * 128 * 144;
    float acc[4][2][4] = {};
    int m0 = blockIdx.y * 128, n0 = blockIdx.x * 64;
    int ks = blockIdx.z * 512;
    mma_loop<128, 64>(g_fib + ks, 1024, g_Wff2 + (size_t)ks * ND, ND,
                      512, m0, n0, acc, sA, sB);
    epi_f32<128, 64>(acc, g_y2p + (size_t)blockIdx.z * NTOK * ND, ND, m0, n0, nullptr);
}

// ---------------- launch ----------------
extern "C" void kernel_launch(void* const* d_in, const int* in_sizes, int n_in,
                              void* d_out, int out_size) {
    const float* x     = (const float*)d_in[0];
    const float* Wq    = (const float*)d_in[1];
    const float* Wkv   = (const float*)d_in[2];
    const float* Wout  = (const float*)d_in[3];
    const float* bout  = (const float*)d_in[4];
    const float* g1    = (const float*)d_in[5];
    const float* beta1 = (const float*)d_in[6];
    const float* Wff1  = (const float*)d_in[7];
    const float* bff1  = (const float*)d_in[8];
    const float* Wff2  = (const float*)d_in[9];
    const float* bff2  = (const float*)d_in[10];
    const float* g2    = (const float*)d_in[11];
    const float* beta2 = (const float*)d_in[12];
    float* out = (float*)d_out;

    static int attr_set = 0;
    if (!attr_set) {
        cudaFuncSetAttribute(k_attn, cudaFuncAttributeMaxDynamicSharedMemorySize, SATT_SZ);
        cudaFuncSetAttribute(k_qkv,  cudaFuncAttributeMaxDynamicSharedMemorySize, SM_QKV);
        cudaFuncSetAttribute(k_wout, cudaFuncAttributeMaxDynamicSharedMemorySize, SM_QKV);
        cudaFuncSetAttribute(k_ff1g, cudaFuncAttributeMaxDynamicSharedMemorySize, SM_G64);
        cudaFuncSetAttribute(k_ff2,  cudaFuncAttributeMaxDynamicSharedMemorySize, SM_G64);
        attr_set = 1;
    }

    k_prep <<<2176, 256>>>((const float4*)Wq, (const float4*)Wkv,
                           (const float4*)Wff1, (const float4*)Wff2, x);
    k_qkv  <<<dim3(12, 32), 256, SM_QKV>>>();
    k_attn <<<148, 512, SATT_SZ>>>((const float4*)Wout);
    k_wout <<<dim3(16, 4, 4), 256, SM_QKV>>>();
    k_ln   <<<4096, 256>>>(1, g1, beta1, bout, nullptr);
    k_ff1g <<<dim3(16, 32), 256, SM_G64>>>(bff1);
    k_ff2  <<<dim3(4, 32, 2), 256, SM_G64>>>();
    k_ln   <<<4096, 256>>>(2, g2, beta2, bff2, out);
}

// round 16
// speedup vs baseline: 1.5616x; 1.5616x over previous
#include <cuda_runtime.h>
#include <cuda_bf16.h>
#include <math.h>
#include <stdint.h>

#define NB     2
#define NSEQ   256
#define NM     8
#define ND     256
#define NH     8
#define NDH    64
#define NINNER 512
#define NTOK   (NB*NSEQ*NM)          // 4096
#define NBN    (NB*NSEQ)             // 512
typedef __nv_bfloat16 bf16;
typedef __nv_bfloat162 bf162;

#define QSCALE 0.18033688011112042f   // 0.125 * log2(e): exp(S) == exp2(S')

// ---------------- scratch ----------------
__device__ float g_xt [NTOK*ND];
__device__ bf16  g_xtb[NTOK*ND];
__device__ bf16  g_qb [NTOK*NINNER];
__device__ bf16  g_kvb[NTOK*2*NINNER];
__device__ bf16  g_aob[(size_t)NBN*4096];
__device__ float g_wp [(size_t)4*NBN*2048];            // wout split-K partials (16.8MB)
__device__ float g_x2 [NTOK*ND];
__device__ bf16  g_x2b[NTOK*ND];
__device__ bf16  g_fib[(size_t)NTOK*1024];
__device__ float g_y2p[(size_t)2*NTOK*ND];             // ff2 split-K partials (8.4MB)
// bf16 weights
__device__ bf16  g_Wq  [256*512];
__device__ bf16  g_Wkv [256*1024];
__device__ bf16  g_Wout[(size_t)4096*2048];
__device__ bf16  g_Wff1[256*2048];
__device__ bf16  g_Wff2[1024*256];

// ---------------- ptx helpers ----------------
__device__ __forceinline__ uint32_t smaddr(const void* p) {
    return (uint32_t)__cvta_generic_to_shared(p);
}
__device__ __forceinline__ void cpa16(uint32_t dst, const void* src) {
    asm volatile("cp.async.cg.shared.global [%0], [%1], 16;\n" :: "r"(dst), "l"(src) : "memory");
}
__device__ __forceinline__ void cpa_commit() { asm volatile("cp.async.commit_group;\n" ::: "memory"); }
__device__ __forceinline__ void cpa_wait0()  { asm volatile("cp.async.wait_group 0;\n" ::: "memory"); }
__device__ __forceinline__ void cpa_wait1()  { asm volatile("cp.async.wait_group 1;\n" ::: "memory"); }

__device__ __forceinline__ void bar_sync(int id, int cnt) {
    asm volatile("bar.sync %0, %1;" :: "r"(id), "r"(cnt) : "memory");
}
__device__ __forceinline__ void bar_arrive(int id, int cnt) {
    asm volatile("bar.arrive %0, %1;" :: "r"(id), "r"(cnt) : "memory");
}
__device__ __forceinline__ float fex2(float x) {
    float r;
    asm("ex2.approx.f32 %0, %1;" : "=f"(r) : "f"(x));
    return r;
}

__device__ __forceinline__ void ldsm4(uint32_t& r0, uint32_t& r1, uint32_t& r2, uint32_t& r3, uint32_t a) {
    asm volatile("ldmatrix.sync.aligned.m8n8.x4.shared.b16 {%0,%1,%2,%3}, [%4];"
                 : "=r"(r0), "=r"(r1), "=r"(r2), "=r"(r3) : "r"(a));
}
__device__ __forceinline__ void ldsm2(uint32_t& r0, uint32_t& r1, uint32_t a) {
    asm volatile("ldmatrix.sync.aligned.m8n8.x2.shared.b16 {%0,%1}, [%2];"
                 : "=r"(r0), "=r"(r1) : "r"(a));
}
__device__ __forceinline__ void ldsm2t(uint32_t& r0, uint32_t& r1, uint32_t a) {
    asm volatile("ldmatrix.sync.aligned.m8n8.x2.trans.shared.b16 {%0,%1}, [%2];"
                 : "=r"(r0), "=r"(r1) : "r"(a));
}
__device__ __forceinline__ void mma_bf16(float* c, const uint32_t* a, const uint32_t* b) {
    asm volatile(
        "mma.sync.aligned.m16n8k16.row.col.f32.bf16.bf16.f32 "
        "{%0,%1,%2,%3}, {%4,%5,%6,%7}, {%8,%9}, {%0,%1,%2,%3};\n"
        : "+f"(c[0]), "+f"(c[1]), "+f"(c[2]), "+f"(c[3])
        : "r"(a[0]), "r"(a[1]), "r"(a[2]), "r"(a[3]), "r"(b[0]), "r"(b[1]));
}

// ---------------- dense GEMM building blocks (K-chunk 64, dynamic smem) ----------------
// A smem: [BM rows][144B] (64 bf16 + 16B pad). B smem: [64 rows][BN*2+16].

template<int BM, int BN>
__device__ __forceinline__ void g2s64(const bf16* __restrict__ A, int lda,
                                      const bf16* __restrict__ B, int ldb,
                                      int m0, int n0, int k0,
                                      uint32_t aB, uint32_t bB, int tid)
{
    #pragma unroll
    for (int i = tid; i < BM * 8; i += 256) {
        int r = i >> 3, c = i & 7;
        cpa16(aB + r * 144 + c * 16, A + (size_t)(m0 + r) * lda + k0 + c * 8);
    }
    constexpr int NC = BN / 8, SBv = BN * 2 + 16;
    #pragma unroll
    for (int i = tid; i < 64 * NC; i += 256) {
        int kr = i / NC, c = i % NC;
        cpa16(bB + kr * SBv + c * 16, B + (size_t)(k0 + kr) * ldb + n0 + c * 8);
    }
    cpa_commit();
}

template<int BM, int BN>
__device__ __forceinline__ void smma64(uint32_t aB, uint32_t bB, int lane,
                                       int wm0, int wn0, float acc[][BN/32][4])
{
    constexpr int MT = BM / 32, NT = BN / 32, SBv = BN * 2 + 16;
    #pragma unroll
    for (int s = 0; s < 4; s++) {
        uint32_t af[MT][4], bf2[NT][2];
        #pragma unroll
        for (int mi = 0; mi < MT; mi++)
            ldsm4(af[mi][0], af[mi][1], af[mi][2], af[mi][3],
                  aB + (wm0 + mi * 16 + (lane & 15)) * 144 + s * 32 + (lane & 16));
        #pragma unroll
        for (int ni = 0; ni < NT; ni++)
            ldsm2t(bf2[ni][0], bf2[ni][1],
                   bB + (s * 16 + (lane & 15)) * SBv + (wn0 + ni * 8) * 2);
        #pragma unroll
        for (int mi = 0; mi < MT; mi++)
            #pragma unroll
            for (int ni = 0; ni < NT; ni++)
                mma_bf16(acc[mi][ni], af[mi], bf2[ni]);
    }
}

template<int BM, int BN>
__device__ __forceinline__ void mma_loop(const bf16* __restrict__ A, int lda,
                                         const bf16* __restrict__ B, int ldb,
                                         int K, int m0, int n0,
                                         float acc[][BN/32][4],
                                         unsigned char* sAbuf, unsigned char* sBbuf)
{
    constexpr int SBv = BN * 2 + 16;
    const int tid = threadIdx.x, lane = tid & 31, warp = tid >> 5;
    const int wm0 = (warp >> 2) * (BM / 2), wn0 = (warp & 3) * (BN / 4);
    uint32_t aB0 = smaddr(sAbuf), aB1 = aB0 + BM * 144;
    uint32_t bB0 = smaddr(sBbuf), bB1 = bB0 + 64 * SBv;

    g2s64<BM, BN>(A, lda, B, ldb, m0, n0, 0, aB0, bB0, tid);
    const int nch = K >> 6;
    for (int i = 0; i < nch; i++) {
        cpa_wait0();
        __syncthreads();
        uint32_t aB = (i & 1) ? aB1 : aB0, bB = (i & 1) ? bB1 : bB0;
        if (i + 1 < nch)
            g2s64<BM, BN>(A, lda, B, ldb, m0, n0, (i + 1) * 64,
                          (i & 1) ? aB0 : aB1, (i & 1) ? bB0 : bB1, tid);
        smma64<BM, BN>(aB, bB, lane, wm0, wn0, acc);
        __syncthreads();
    }
}

// smem budgets
#define SM_QKV  (2*128*144 + 2*64*272)   // 71680
#define SM_G64  (2*128*144 + 2*64*144)   // 55296
#define SM_FF1  (2*128*144 + 4*64*144)   // 73728

// ---------------- epilogue helpers ----------------
template<int BM, int BN>
__device__ __forceinline__ void epi_f32(float acc[][BN/32][4], float* C, int ldc,
                                        int m0, int n0, const float* bias)
{
    const int lane = threadIdx.x & 31, warp = threadIdx.x >> 5;
    const int lr = lane >> 2, lc = lane & 3;
    const int wm0 = (warp >> 2) * (BM / 2), wn0 = (warp & 3) * (BN / 4);
    #pragma unroll
    for (int mi = 0; mi < BM / 32; mi++) {
        int row = m0 + wm0 + mi * 16 + lr;
        #pragma unroll
        for (int ni = 0; ni < BN / 32; ni++) {
            int col = n0 + wn0 + ni * 8 + 2 * lc;
            float bx = 0.f, by = 0.f;
            if (bias) { bx = bias[col]; by = bias[col + 1]; }
            *(float2*)(C + (size_t)row * ldc + col) =
                make_float2(acc[mi][ni][0] + bx, acc[mi][ni][1] + by);
            *(float2*)(C + (size_t)(row + 8) * ldc + col) =
                make_float2(acc[mi][ni][2] + bx, acc[mi][ni][3] + by);
        }
    }
}

template<int BM, int BN>
__device__ __forceinline__ void epi_bf16(float acc[][BN/32][4], bf16* C, int ldc,
                                         int m0, int n0, float alpha)
{
    const int lane = threadIdx.x & 31, warp = threadIdx.x >> 5;
    const int lr = lane >> 2, lc = lane & 3;
    const int wm0 = (warp >> 2) * (BM / 2), wn0 = (warp & 3) * (BN / 4);
    #pragma unroll
    for (int mi = 0; mi < BM / 32; mi++) {
        int row = m0 + wm0 + mi * 16 + lr;
        #pragma unroll
        for (int ni = 0; ni < BN / 32; ni++) {
            int col = n0 + wn0 + ni * 8 + 2 * lc;
            *(bf162*)(C + (size_t)row * ldc + col) =
                __floats2bfloat162_rn(acc[mi][ni][0] * alpha, acc[mi][ni][1] * alpha);
            *(bf162*)(C + (size_t)(row + 8) * ldc + col) =
                __floats2bfloat162_rn(acc[mi][ni][2] * alpha, acc[mi][ni][3] * alpha);
        }
    }
}

// ---------------- kernels ----------------

// merged: small weight conversions (Wq/Wkv/Wff1/Wff2) + input transpose.
__global__ __launch_bounds__(256) void k_prep(const float4* __restrict__ Wq,
                                              const float4* __restrict__ Wkv,
                                              const float4* __restrict__ Wff1,
                                              const float4* __restrict__ Wff2,
                                              const float* __restrict__ x)
{
    if (blockIdx.x < 1152) {
        int i = blockIdx.x * 256 + threadIdx.x;
        const float4* src; bf162* dst; int off;
        if      (i < 32768)  { src = Wq;   dst = (bf162*)g_Wq;   off = 0; }
        else if (i < 98304)  { src = Wkv;  dst = (bf162*)g_Wkv;  off = 32768; }
        else if (i < 229376) { src = Wff1; dst = (bf162*)g_Wff1; off = 98304; }
        else                 { src = Wff2; dst = (bf162*)g_Wff2; off = 229376; }
        int j = i - off;
        float4 v = src[j];
        dst[2 * j]     = __floats2bfloat162_rn(v.x, v.y);
        dst[2 * j + 1] = __floats2bfloat162_rn(v.z, v.w);
        return;
    }
    __shared__ float tile[32][33];
    int bi = blockIdx.x - 1152;
    int bx = bi & 7, by = (bi >> 3) & 7, zi = bi >> 6;
    int b = zi >> 3, m = zi & 7;
    int n0 = bx * 32, d0 = by * 32;
    int tx = threadIdx.x & 31, ty = threadIdx.x >> 5;
    #pragma unroll
    for (int r = 0; r < 4; r++) {
        int d = d0 + ty + r * 8;
        tile[ty + r * 8][tx] =
            x[((size_t)(b * ND + d) * NM + m) * NSEQ + n0 + tx];
    }
    __syncthreads();
    #pragma unroll
    for (int r = 0; r < 4; r++) {
        int n = n0 + ty + r * 8;
        int d = d0 + tx;
        float v = tile[tx][ty + r * 8];
        size_t o = ((size_t)(b * NSEQ + n) * NM + m) * ND + d;
        g_xt[o]  = v;
        g_xtb[o] = __float2bfloat16(v);
    }
}

// fused Q + KV projection. blockIdx.x<4 -> Q tile (x QSCALE), else KV tile.
__global__ __launch_bounds__(256) void k_qkv() {
    extern __shared__ unsigned char dsm[];
    unsigned char* sA = dsm;
    unsigned char* sB = dsm + 2 * 128 * 144;
    float acc[4][4][4] = {};
    int m0 = blockIdx.y * 128;
    if (blockIdx.x < 4) {
        int n0 = blockIdx.x * 128;
        mma_loop<128, 128>(g_xtb, ND, g_Wq, NINNER, ND, m0, n0, acc, sA, sB);
        epi_bf16<128, 128>(acc, g_qb, NINNER, m0, n0, QSCALE);
    } else {
        int n0 = (blockIdx.x - 4) * 128;
        mma_loop<128, 128>(g_xtb, ND, g_Wkv, 2 * NINNER, ND, m0, n0, acc, sA, sB);
        epi_bf16<128, 128>(acc, g_kvb, 2 * NINNER, m0, n0, 1.f);
    }
}

// ============ warp-specialized fused attention + hidden Wout conversion ============
// Blocks 0-127: attention. Blocks 128-147: convert Wout fp32->bf16 on idle SMs.
#define SATT_K    0
#define SATT_Q0   36864
#define SATT_Q1   73728
#define SATT_P0   110592
#define SATT_P1   147456
#define SATT_V0   184320
#define SATT_V1   193536
#define SATT_PART 202752
#define SATT_RSC  204800
#define SATT_SZ   205056
// barrier ids: FULL0=1 FULL1=2 EMPTY0=3 EMPTY1=4, producer-local=5, consumer-local=6

__global__ void __launch_bounds__(512, 1) k_attn(const float4* __restrict__ WoutSrc) {
    if (blockIdx.x >= 128) {
        const size_t total = (size_t)4096 * 2048 / 4;
        bf162* dst = (bf162*)g_Wout;
        for (size_t i = (size_t)(blockIdx.x - 128) * 512 + threadIdx.x;
             i < total; i += (size_t)20 * 512) {
            float4 v = WoutSrc[i];
            dst[2 * i]     = __floats2bfloat162_rn(v.x, v.y);
            dst[2 * i + 1] = __floats2bfloat162_rn(v.z, v.w);
        }
        return;
    }
    extern __shared__ unsigned char smem[];
    const uint32_t base = smaddr(smem);
    const int tid = threadIdx.x, lane = tid & 31, warp = tid >> 5;
    const int lr = lane >> 2, lc = lane & 3;
    const int e = blockIdx.x;
    const int z = e & 7, h = (e >> 3) & 7, b = e >> 6;

    const bf16* Qe = g_qb  + (size_t)(b * 2048) * 512  + h * 64;
    const bf16* Ke = g_kvb + (size_t)(b * 2048) * 1024 + h * 64;
    const bf16* Ve = g_kvb + (size_t)(b * 2048) * 1024 + 512 + h * 64;
    float* part = (float*)(smem + SATT_PART);
    float* rsc  = (float*)(smem + SATT_RSC);

    const uint32_t qB[2] = { base + SATT_Q0, base + SATT_Q1 };
    const uint32_t pB[2] = { base + SATT_P0, base + SATT_P1 };
    const uint32_t vB[2] = { base + SATT_V0, base + SATT_V1 };

    if (warp < 8) {
        // ---------------- PRODUCER ----------------
        const int ptid = tid;
        const int wm = warp >> 1, wn = warp & 1;
        auto loadK = [&]() {
            #pragma unroll
            for (int q = 0; q < 8; q++) {
                int idx = ptid + q * 256, row = idx >> 3, cc = idx & 7;
                cpa16(base + SATT_K + row * 144 + cc * 16,
                      Ke + (size_t)(row * 8 + z) * 1024 + cc * 8);
            }
        };
        auto loadQ = [&](int m, uint32_t dst) {
            #pragma unroll
            for (int q = 0; q < 8; q++) {
                int idx = ptid + q * 256, row = idx >> 3, cc = idx & 7;
                cpa16(dst + row * 144 + cc * 16,
                      Qe + (size_t)(row * 8 + m) * 512 + cc * 8);
            }
        };
        loadK();
        loadQ(0, qB[0]);
        cpa_commit();

        for (int c = 0; c < 32; c++) {
            const int m = c >> 2, j0 = (c & 3) << 6, s = c & 1;
            if ((c & 3) == 0) {
                if (m < 7) loadQ(m + 1, qB[(m + 1) & 1]);
                cpa_commit();
                cpa_wait1();
                bar_sync(5, 256);
            }
            bar_sync(3 + s, 512);
            const uint32_t qb = qB[m & 1];
            float sa[4][4][4] = {};
            #pragma unroll
            for (int s4 = 0; s4 < 4; s4++) {
                uint32_t af[4][4], bf2[4][2];
                #pragma unroll
                for (int mi = 0; mi < 4; mi++)
                    ldsm4(af[mi][0], af[mi][1], af[mi][2], af[mi][3],
                          qb + (wm * 64 + mi * 16 + (lane & 15)) * 144 + s4 * 32 + (lane & 16));
                #pragma unroll
                for (int ni = 0; ni < 4; ni++)
                    ldsm2(bf2[ni][0], bf2[ni][1],
                          base + SATT_K + (j0 + wn * 32 + ni * 8 + (lane & 7)) * 144
                          + s4 * 32 + ((lane >> 3) & 1) * 16);
                #pragma unroll
                for (int mi = 0; mi < 4; mi++)
                    #pragma unroll
                    for (int ni = 0; ni < 4; ni++)
                        mma_bf16(sa[mi][ni], af[mi], bf2[ni]);
            }
            float cs[4][2];
            #pragma unroll
            for (int ni = 0; ni < 4; ni++) { cs[ni][0] = 0.f; cs[ni][1] = 0.f; }
            #pragma unroll
            for (int mi = 0; mi < 4; mi++)
                #pragma unroll
                for (int ni = 0; ni < 4; ni++) {
                    float p0 = fex2(sa[mi][ni][0]);
                    float p1 = fex2(sa[mi][ni][1]);
                    float p2 = fex2(sa[mi][ni][2]);
                    float p3 = fex2(sa[mi][ni][3]);
                    sa[mi][ni][0] = p0; sa[mi][ni][1] = p1;
                    sa[mi][ni][2] = p2; sa[mi][ni][3] = p3;
                    cs[ni][0] += p0 + p2; cs[ni][1] += p1 + p3;
                }
            #pragma unroll
            for (int ni = 0; ni < 4; ni++) {
                float a = cs[ni][0], bq = cs[ni][1];
                #pragma unroll
                for (int o = 4; o <= 16; o <<= 1) {
                    a  += __shfl_xor_sync(0xffffffffu, a,  o);
                    bq += __shfl_xor_sync(0xffffffffu, bq, o);
                }
                if (lane < 4) {
                    int col = wn * 32 + ni * 8 + 2 * lane;
                    part[s * 256 + col * 4 + wm]       = a;
                    part[s * 256 + (col + 1) * 4 + wm] = bq;
                }
            }
            const uint32_t po = (s ? SATT_P1 : SATT_P0);
            #pragma unroll
            for (int ni = 0; ni < 4; ni++) {
                int col = wn * 32 + ni * 8 + 2 * lc;
                #pragma unroll
                for (int mi = 0; mi < 4; mi++) {
                    int row = wm * 64 + mi * 16 + lr;
                    *(bf162*)(smem + po + row * 144 + col * 2) =
                        __floats2bfloat162_rn(sa[mi][ni][0], sa[mi][ni][1]);
                    *(bf162*)(smem + po + (row + 8) * 144 + col * 2) =
                        __floats2bfloat162_rn(sa[mi][ni][2], sa[mi][ni][3]);
                }
            }
            bar_arrive(1 + s, 512);
        }
    } else {
        // ---------------- CONSUMER ----------------
        const int ctid = tid - 256;
        const int cw = warp - 8;
        const int wm = cw >> 1, wn = cw & 1;
        auto loadV = [&](int m, int j0, uint32_t dst) {
            #pragma unroll
            for (int q = 0; q < 2; q++) {
                int idx = ctid + q * 256, row = idx >> 3, cc = idx & 7;
                cpa16(dst + row * 144 + cc * 16,
                      Ve + (size_t)((j0 + row) * 8 + m) * 1024 + cc * 8);
            }
        };
        bar_arrive(3, 512);
        bar_arrive(4, 512);
        loadV(0, 0, vB[0]);
        cpa_commit();

        float oacc[4][4][4] = {};
        for (int c = 0; c < 32; c++) {
            const int s = c & 1;
            bar_sync(1 + s, 512);
            if (c < 31) {
                int cn = c + 1;
                loadV(cn >> 2, (cn & 3) << 6, vB[cn & 1]);
                cpa_commit();
                cpa_wait1();
            } else {
                cpa_wait0();
            }
            if (ctid < 64)
                rsc[ctid] = 1.f / (part[s * 256 + 4 * ctid]     + part[s * 256 + 4 * ctid + 1]
                                 + part[s * 256 + 4 * ctid + 2] + part[s * 256 + 4 * ctid + 3]);
            bar_sync(6, 256);
            const uint32_t vb = vB[s], pb = pB[s];
            {
                #pragma unroll
                for (int q = 0; q < 2; q++) {
                    int idx = ctid + q * 256, row = idx >> 3, cc = idx & 7;
                    float r = rsc[row];
                    bf162* vp2 = (bf162*)(smem + (vb - base) + row * 144 + cc * 16);
                    #pragma unroll
                    for (int qq = 0; qq < 4; qq++) {
                        float2 f = __bfloat1622float2(vp2[qq]);
                        f.x *= r; f.y *= r;
                        vp2[qq] = __float22bfloat162_rn(f);
                    }
                }
            }
            bar_sync(6, 256);
            #pragma unroll
            for (int s4 = 0; s4 < 4; s4++) {
                uint32_t af[4][4], bf2[4][2];
                #pragma unroll
                for (int mi = 0; mi < 4; mi++)
                    ldsm4(af[mi][0], af[mi][1], af[mi][2], af[mi][3],
                          pb + (wm * 64 + mi * 16 + (lane & 15)) * 144 + s4 * 32 + (lane & 16));
                #pragma unroll
                for (int ni = 0; ni < 4; ni++)
                    ldsm2t(bf2[ni][0], bf2[ni][1],
                           vb + (s4 * 16 + (lane & 15)) * 144 + (wn * 32 + ni * 8) * 2);
                #pragma unroll
                for (int mi = 0; mi < 4; mi++)
                    #pragma unroll
                    for (int ni = 0; ni < 4; ni++)
                        mma_bf16(oacc[mi][ni], af[mi], bf2[ni]);
            }
            bar_arrive(3 + s, 512);
        }
        bf16* Ob = g_aob + (size_t)(b * 256) * 4096 + z * 512 + h * 64;
        #pragma unroll
        for (int mi = 0; mi < 4; mi++) {
            int row = wm * 64 + mi * 16 + lr;
            #pragma unroll
            for (int ni = 0; ni < 4; ni++) {
                int col = wn * 32 + ni * 8 + 2 * lc;
                *(bf162*)(Ob + (size_t)row * 4096 + col) =
                    __floats2bfloat162_rn(oacc[mi][ni][0], oacc[mi][ni][1]);
                *(bf162*)(Ob + (size_t)(row + 8) * 4096 + col) =
                    __floats2bfloat162_rn(oacc[mi][ni][2], oacc[mi][ni][3]);
            }
        }
    }
}

// Wout split-K x4, 128x64 tiles (512 CTAs): partial GEMM over K slice -> g_wp[z]
__global__ __launch_bounds__(256) void k_wout() {
    extern __shared__ unsigned char dsm[];
    unsigned char* sA = dsm;
    unsigned char* sB = dsm + 2 * 128 * 144;
    float acc[4][2][4] = {};
    int m0 = blockIdx.y * 128, n0 = blockIdx.x * 64;
    int ks = blockIdx.z * 1024;
    mma_loop<128, 64>(g_aob + ks, 4096, g_Wout + (size_t)ks * 2048, 2048,
                      1024, m0, n0, acc, sA, sB);
    epi_f32<128, 64>(acc, g_wp + (size_t)blockIdx.z * NBN * 2048, 2048, m0, n0, nullptr);
}

// residual + LayerNorm with split-K partial reduction.
__global__ __launch_bounds__(256) void k_ln(int mode,
                                            const float* __restrict__ g,
                                            const float* __restrict__ beta,
                                            const float* __restrict__ bias,
                                            float* __restrict__ out) {
    int t = blockIdx.x, d = threadIdx.x;
    float xv, yv;
    if (mode == 1) {
        int bn = t >> 3, m = t & 7;
        size_t idx = (size_t)bn * 2048 + m * 256 + d;
        xv = g_xt[(size_t)t * ND + d];
        yv = g_wp[idx] + g_wp[idx + (size_t)NBN * 2048]
           + g_wp[idx + (size_t)2 * NBN * 2048] + g_wp[idx + (size_t)3 * NBN * 2048]
           + bias[m * 256 + d];
    } else {
        size_t idx = (size_t)t * ND + d;
        xv = g_x2[idx];
        yv = g_y2p[idx] + g_y2p[idx + (size_t)NTOK * ND] + bias[d];
    }
    float v = xv + yv;
    float s = v, s2 = v * v;
    #pragma unroll
    for (int o = 16; o; o >>= 1) {
        s  += __shfl_xor_sync(0xffffffffu, s,  o);
        s2 += __shfl_xor_sync(0xffffffffu, s2, o);
    }
    __shared__ float sh[16];
    int w = d >> 5, l = d & 31;
    if (l == 0) { sh[w] = s; sh[8 + w] = s2; }
    __syncthreads();
    if (d == 0) {
        float ts = 0.f, ts2 = 0.f;
        #pragma unroll
        for (int i = 0; i < 8; i++) { ts += sh[i]; ts2 += sh[8 + i]; }
        float mu  = ts * (1.f / 256.f);
        float var = ts2 * (1.f / 256.f) - mu * mu;
        sh[0] = mu;
        sh[1] = rsqrtf(var + 1e-5f);
    }
    __syncthreads();
    float r = (v - sh[0]) * sh[1] * g[d] + beta[d];
    if (mode == 1) {
        g_x2 [(size_t)t * ND + d] = r;
        g_x2b[(size_t)t * ND + d] = __float2bfloat16(r);
    } else {
        out[(size_t)t * ND + d] = r;
    }
}

// FFN1 + GEGLU fused, DUAL-B mainloop: one A tile, both a/gate B tiles per K-chunk.
__global__ __launch_bounds__(256) void k_ff1g(const float* __restrict__ bias) {
    extern __shared__ unsigned char dsm[];
    unsigned char* sA = dsm;
    unsigned char* sB = dsm + 2 * 128 * 144;
    const int tid = threadIdx.x, lane = tid & 31, warp = tid >> 5;
    const int wm0 = (warp >> 2) * 64, wn0 = (warp & 3) * 16;
    const int m0 = blockIdx.y * 128, n0 = blockIdx.x * 64;
    float aA[4][2][4] = {};
    float aG[4][2][4] = {};
    uint32_t aB0 = smaddr(sA), aB1 = aB0 + 128 * 144;
    uint32_t bB0 = smaddr(sB), bB1 = bB0 + 2 * 64 * 144;

    auto g2s = [&](int k0, uint32_t aB, uint32_t bB) {
        #pragma unroll
        for (int i = tid; i < 128 * 8; i += 256) {
            int r = i >> 3, c = i & 7;
            cpa16(aB + r * 144 + c * 16, g_x2b + (size_t)(m0 + r) * ND + k0 + c * 8);
        }
        #pragma unroll
        for (int i = tid; i < 64 * 8; i += 256) {
            int kr = i >> 3, c = i & 7;
            cpa16(bB + kr * 144 + c * 16,
                  g_Wff1 + (size_t)(k0 + kr) * 2048 + n0 + c * 8);
        }
        #pragma unroll
        for (int i = tid; i < 64 * 8; i += 256) {
            int kr = i >> 3, c = i & 7;
            cpa16(bB + 64 * 144 + kr * 144 + c * 16,
                  g_Wff1 + (size_t)(k0 + kr) * 2048 + n0 + 1024 + c * 8);
        }
        cpa_commit();
    };

    g2s(0, aB0, bB0);
    #pragma unroll
    for (int i = 0; i < 4; i++) {                 // K=256, 4 chunks of 64
        cpa_wait0();
        __syncthreads();
        uint32_t aB = (i & 1) ? aB1 : aB0, bB = (i & 1) ? bB1 : bB0;
        if (i + 1 < 4)
            g2s((i + 1) * 64, (i & 1) ? aB0 : aB1, (i & 1) ? bB0 : bB1);
        #pragma unroll
        for (int s = 0; s < 4; s++) {
            uint32_t af[4][4], ba[2][2], bg[2][2];
            #pragma unroll
            for (int mi = 0; mi < 4; mi++)
                ldsm4(af[mi][0], af[mi][1], af[mi][2], af[mi][3],
                      aB + (wm0 + mi * 16 + (lane & 15)) * 144 + s * 32 + (lane & 16));
            #pragma unroll
            for (int ni = 0; ni < 2; ni++) {
                ldsm2t(ba[ni][0], ba[ni][1],
                       bB + (s * 16 + (lane & 15)) * 144 + (wn0 + ni * 8) * 2);
                ldsm2t(bg[ni][0], bg[ni][1],
                       bB + 64 * 144 + (s * 16 + (lane & 15)) * 144 + (wn0 + ni * 8) * 2);
            }
            #pragma unroll
            for (int mi = 0; mi < 4; mi++)
                #pragma unroll
                for (int ni = 0; ni < 2; ni++) {
                    mma_bf16(aA[mi][ni], af[mi], ba[ni]);
                    mma_bf16(aG[mi][ni], af[mi], bg[ni]);
                }
        }
        __syncthreads();
    }

    const int lr = lane >> 2, lc = lane & 3;
    #pragma unroll
    for (int mi = 0; mi < 4; mi++) {
        int row = m0 + wm0 + mi * 16 + lr;
        #pragma unroll
        for (int ni = 0; ni < 2; ni++) {
            int col = n0 + wn0 + ni * 8 + 2 * lc;
            float ba0 = bias[col],        ba1 = bias[col + 1];
            float bg0 = bias[1024 + col], bg1 = bias[1024 + col + 1];
            #pragma unroll
            for (int half = 0; half < 2; half++) {
                int r = row + half * 8;
                float a0 = aA[mi][ni][2 * half + 0] + ba0;
                float a1 = aA[mi][ni][2 * half + 1] + ba1;
                float gt0 = aG[mi][ni][2 * half + 0] + bg0;
                float gt1 = aG[mi][ni][2 * half + 1] + bg1;
                float v0 = a0 * 0.5f * gt0 * (1.f + erff(gt0 * 0.70710678118654752f));
                float v1 = a1 * 0.5f * gt1 * (1.f + erff(gt1 * 0.70710678118654752f));
                *(bf162*)(g_fib + (size_t)r * 1024 + col) = __floats2bfloat162_rn(v0, v1);
            }
        }
    }
}

// FF2 split-K x2: partial GEMM over K slice -> g_y2p[z]
__global__ __launch_bounds__(256) void k_ff2() {
    extern __shared__ unsigned char dsm[];
    unsigned char* sA = dsm;
    unsigned char* sB = dsm + 2 * 128 * 144;
    float acc[4][2][4] = {};
    int m0 = blockIdx.y * 128, n0 = blockIdx.x * 64;
    int ks = blockIdx.z * 512;
    mma_loop<128, 64>(g_fib + ks, 1024, g_Wff2 + (size_t)ks * ND, ND,
                      512, m0, n0, acc, sA, sB);
    epi_f32<128, 64>(acc, g_y2p + (size_t)blockIdx.z * NTOK * ND, ND, m0, n0, nullptr);
}

// ---------------- launch ----------------
extern "C" void kernel_launch(void* const* d_in, const int* in_sizes, int n_in,
                              void* d_out, int out_size) {
    const float* x     = (const float*)d_in[0];
    const float* Wq    = (const float*)d_in[1];
    const float* Wkv   = (const float*)d_in[2];
    const float* Wout  = (const float*)d_in[3];
    const float* bout  = (const float*)d_in[4];
    const float* g1    = (const float*)d_in[5];
    const float* beta1 = (const float*)d_in[6];
    const float* Wff1  = (const float*)d_in[7];
    const float* bff1  = (const float*)d_in[8];
    const float* Wff2  = (const float*)d_in[9];
    const float* bff2  = (const float*)d_in[10];
    const float* g2    = (const float*)d_in[11];
    const float* beta2 = (const float*)d_in[12];
    float* out = (float*)d_out;

    static int attr_set = 0;
    if (!attr_set) {
        cudaFuncSetAttribute(k_attn, cudaFuncAttributeMaxDynamicSharedMemorySize, SATT_SZ);
        cudaFuncSetAttribute(k_qkv,  cudaFuncAttributeMaxDynamicSharedMemorySize, SM_QKV);
        cudaFuncSetAttribute(k_wout, cudaFuncAttributeMaxDynamicSharedMemorySize, SM_G64);
        cudaFuncSetAttribute(k_ff1g, cudaFuncAttributeMaxDynamicSharedMemorySize, SM_FF1);
        cudaFuncSetAttribute(k_ff2,  cudaFuncAttributeMaxDynamicSharedMemorySize, SM_G64);
        attr_set = 1;
    }

    k_prep <<<2176, 256>>>((const float4*)Wq, (const float4*)Wkv,
                           (const float4*)Wff1, (const float4*)Wff2, x);
    k_qkv  <<<dim3(12, 32), 256, SM_QKV>>>();
    k_attn <<<148, 512, SATT_SZ>>>((const float4*)Wout);
    k_wout <<<dim3(32, 4, 4), 256, SM_G64>>>();
    k_ln   <<<4096, 256>>>(1, g1, beta1, bout, nullptr);
    k_ff1g <<<dim3(16, 32), 256, SM_FF1>>>(bff1);
    k_ff2  <<<dim3(4, 32, 2), 256, SM_G64>>>();
    k_ln   <<<4096, 256>>>(2, g2, beta2, bff2, out);
}